// round 6
// baseline (speedup 1.0000x reference)
#include <cuda_runtime.h>
#include <math.h>

#define S_LEN 512
#define B_DIM 256
#define IN_DIM 256
#define BR_DIM 128
#define H_DIM 512
#define G_DIM 2048                 // 4*H
#define M_DIM (S_LEN * B_DIM)     // 131072

#define KC 32
#define NTHREADS 256
#define NCTAS 128

typedef unsigned long long u64;

// ---------------- device scratch (no allocations allowed) ----------------
__device__ float g_gx[(size_t)S_LEN * B_DIM * G_DIM];   // input-side gate preacts (1 GiB, reused per layer)
__device__ float g_hs0[(size_t)S_LEN * B_DIM * H_DIM];  // layer-0 outputs
__device__ float g_h0[2][B_DIM * H_DIM];
__device__ float g_h1[2][B_DIM * H_DIM];
__device__ unsigned g_arrive;
__device__ volatile unsigned g_release;

// ---------------- packed f32x2 helpers ----------------
__device__ __forceinline__ u64 pack2(float lo, float hi) {
    u64 r; asm("mov.b64 %0, {%1, %2};" : "=l"(r) : "f"(lo), "f"(hi)); return r;
}
__device__ __forceinline__ void unpack2(u64 v, float& lo, float& hi) {
    asm("mov.b64 {%0, %1}, %2;" : "=f"(lo), "=f"(hi) : "l"(v));
}
__device__ __forceinline__ void fma2(u64& d, u64 a, u64 b) {
    asm("fma.rn.f32x2 %0, %1, %2, %0;" : "+l"(d) : "l"(a), "l"(b));
}
__device__ __forceinline__ float fast_sigmoid(float x) { return 1.0f / (1.0f + __expf(-x)); }
__device__ __forceinline__ float fast_tanh(float x) { return 1.0f - 2.0f / (__expf(2.0f * x) + 1.0f); }

// ---------------- grid-wide sense barrier (128 co-resident CTAs) ----------------
__device__ __forceinline__ void gsync(unsigned gen) {
    __syncthreads();
    if (threadIdx.x == 0) {
        __threadfence();
        unsigned a = atomicAdd(&g_arrive, 1u);
        if (a == NCTAS - 1) {
            g_arrive = 0;
            __threadfence();
            g_release = gen;
        } else {
            while (g_release < gen) { }
            __threadfence();
        }
    }
    __syncthreads();
}

// ---------------- tiled GEMM core (32 rows x 128 cols per CTA) ----------------
// Thread (lane, wrp): row = rowBase+lane; cols = g*H + colBase + 4*wrp + {0..3}, 4 gates.
// As smem: [k][row] stride 33.  Ws smem: [k][g*32+h] rows of 128 floats.
struct StageRegs {
    float a[4];
    float4 w[4];
};

__device__ __forceinline__ void ldg_stage(
    StageRegs& s, const float* __restrict__ A, int ldA, int rowBase,
    const float* __restrict__ W, int colBase, int kc, int tid)
{
    #pragma unroll
    for (int e = 0; e < 4; e++) {
        int lin = tid + NTHREADS * e;
        int k = lin & 31, r = lin >> 5;
        s.a[e] = A[(size_t)(rowBase + r) * ldA + kc + k];
    }
    #pragma unroll
    for (int e = 0; e < 4; e++) {
        int lin4 = tid + NTHREADS * e;       // float4 index, 0..1023
        int k = lin4 >> 5;
        int off = (lin4 & 31) * 4;           // 0..124
        int g = off >> 5, h = off & 31;
        s.w[e] = *(const float4*)&W[(size_t)(kc + k) * G_DIM + g * H_DIM + colBase + h];
    }
}

__device__ __forceinline__ void sts_stage(const StageRegs& s, float* As, float* Ws, int tid) {
    #pragma unroll
    for (int e = 0; e < 4; e++) {
        int lin = tid + NTHREADS * e;
        int k = lin & 31, r = lin >> 5;
        As[k * 33 + r] = s.a[e];
    }
    #pragma unroll
    for (int e = 0; e < 4; e++) {
        ((float4*)Ws)[tid + NTHREADS * e] = s.w[e];
    }
}

__device__ __forceinline__ void compute_chunk(
    u64 acc[4][2], const float* As, const float* Ws, int lane, int wrp)
{
    #pragma unroll
    for (int k = 0; k < KC; k++) {
        float a = As[k * 33 + lane];
        u64 aa = pack2(a, a);
        const ulonglong2* wp = (const ulonglong2*)(Ws + k * 128 + 4 * wrp);
        #pragma unroll
        for (int g = 0; g < 4; g++) {
            ulonglong2 w = wp[g * 8];     // broadcast LDS.128
            fma2(acc[g][0], w.x, aa);
            fma2(acc[g][1], w.y, aa);
        }
    }
}

// Software-pipelined K-segment: LDG 2 chunks ahead, STS 1 ahead, 1 sync/chunk.
__device__ __forceinline__ void gemm_seg(
    u64 acc[4][2], const float* __restrict__ A, int ldA, int Kseg,
    const float* __restrict__ W, int rowBase, int colBase,
    float* As0, float* Ws0, float* As1, float* Ws1)
{
    const int tid = threadIdx.x;
    const int lane = tid & 31;
    const int wrp = tid >> 5;
    float* Asb[2] = {As0, As1};
    float* Wsb[2] = {Ws0, Ws1};
    const int nc = Kseg / KC;

    StageRegs s;
    ldg_stage(s, A, ldA, rowBase, W, colBase, 0, tid);
    sts_stage(s, As0, Ws0, tid);
    if (nc > 1) ldg_stage(s, A, ldA, rowBase, W, colBase, KC, tid);
    __syncthreads();

    for (int c = 0; c < nc; c++) {
        if (c + 1 < nc) sts_stage(s, Asb[(c + 1) & 1], Wsb[(c + 1) & 1], tid);
        if (c + 2 < nc) ldg_stage(s, A, ldA, rowBase, W, colBase, (c + 2) * KC, tid);
        compute_chunk(acc, Asb[c & 1], Wsb[c & 1], lane, wrp);
        __syncthreads();
    }
}

// ---------------- init ----------------
__global__ void __launch_bounds__(NTHREADS, 1) init_kernel() {
    int i = blockIdx.x * blockDim.x + threadIdx.x;
    if (i == 0) { g_arrive = 0; g_release = 0; }
    if (i < B_DIM * H_DIM) {
        g_h0[0][i] = 0.0f;
        g_h1[0][i] = 0.0f;
    }
}

// ---------------- bulk input-side gates ----------------
// layer0: gx = bias0 + x@Wih0 + b@Wbh0   (A rows are flattened [S*B])
__global__ void __launch_bounds__(NTHREADS) bulk0_kernel(
    const float* __restrict__ x, const float* __restrict__ br,
    const float* __restrict__ Wih, const float* __restrict__ Wbh,
    const float* __restrict__ bias)
{
    __shared__ __align__(16) float As0[KC * 33], As1[KC * 33];
    __shared__ __align__(16) float Ws0[KC * 128], Ws1[KC * 128];
    const int tid = threadIdx.x, lane = tid & 31, wrp = tid >> 5;
    const int colBase = blockIdx.x * 32;
    const int rowBase = blockIdx.y * 32;

    u64 acc[4][2];
    #pragma unroll
    for (int g = 0; g < 4; g++) {
        ulonglong2 bv = *(const ulonglong2*)(bias + g * H_DIM + colBase + 4 * wrp);
        acc[g][0] = bv.x; acc[g][1] = bv.y;
    }

    gemm_seg(acc, x, IN_DIM, IN_DIM, Wih, rowBase, colBase, As0, Ws0, As1, Ws1);
    gemm_seg(acc, br, BR_DIM, BR_DIM, Wbh, rowBase, colBase, As0, Ws0, As1, Ws1);

    float* dst = g_gx + (size_t)(rowBase + lane) * G_DIM + colBase + 4 * wrp;
    #pragma unroll
    for (int g = 0; g < 4; g++) {
        ulonglong2 v; v.x = acc[g][0]; v.y = acc[g][1];
        *(ulonglong2*)(dst + g * H_DIM) = v;
    }
}

// layer1: gx = bias1 + hs0@Wih1
__global__ void __launch_bounds__(NTHREADS) bulk1_kernel(
    const float* __restrict__ Wih, const float* __restrict__ bias)
{
    __shared__ __align__(16) float As0[KC * 33], As1[KC * 33];
    __shared__ __align__(16) float Ws0[KC * 128], Ws1[KC * 128];
    const int tid = threadIdx.x, lane = tid & 31, wrp = tid >> 5;
    const int colBase = blockIdx.x * 32;
    const int rowBase = blockIdx.y * 32;

    u64 acc[4][2];
    #pragma unroll
    for (int g = 0; g < 4; g++) {
        ulonglong2 bv = *(const ulonglong2*)(bias + g * H_DIM + colBase + 4 * wrp);
        acc[g][0] = bv.x; acc[g][1] = bv.y;
    }

    gemm_seg(acc, g_hs0, H_DIM, H_DIM, Wih, rowBase, colBase, As0, Ws0, As1, Ws1);

    float* dst = g_gx + (size_t)(rowBase + lane) * G_DIM + colBase + 4 * wrp;
    #pragma unroll
    for (int g = 0; g < 4; g++) {
        ulonglong2 v; v.x = acc[g][0]; v.y = acc[g][1];
        *(ulonglong2*)(dst + g * H_DIM) = v;
    }
}

// ---------------- recurrent persistent kernel (one per layer) ----------------
// layer=0: hprev=g_h0, per-step h also to g_hs0; finals -> out[base], out[base+2BH], gen 1..512
// layer=1: hprev=g_h1, per-step h to out (hs1);  finals -> out[base+BH], out[base+3BH], gen 513..1024
__global__ void __launch_bounds__(NTHREADS, 1) recur_kernel(
    int layer, const float* __restrict__ Whh, float* __restrict__ out)
{
    __shared__ __align__(16) float As0[KC * 33], As1[KC * 33];
    __shared__ __align__(16) float Ws0[KC * 128], Ws1[KC * 128];
    const int tid = threadIdx.x, lane = tid & 31, wrp = tid >> 5;
    const int ht0 = blockIdx.x * 32;  // gridDim.x = 16
    const int bt0 = blockIdx.y * 32;  // gridDim.y = 8
    const int b = bt0 + lane;
    const int h0 = ht0 + 4 * wrp;
    const size_t oidx = (size_t)b * H_DIM + h0;

    float* hb0 = (layer == 0) ? g_h0[0] : g_h1[0];
    float* hb1 = (layer == 0) ? g_h0[1] : g_h1[1];
    float* hstep = (layer == 0) ? g_hs0 : out;
    const unsigned genBase = (layer == 0) ? 0u : (unsigned)S_LEN;

    u64 c01 = 0, c23 = 0;
    u64 hv01 = 0, hv23 = 0;

    for (int t = 0; t < S_LEN; t++) {
        u64 acc[4][2];
        const float* gxr = g_gx + ((size_t)t * B_DIM + b) * G_DIM + h0;
        #pragma unroll
        for (int g = 0; g < 4; g++) {
            ulonglong2 v = *(const ulonglong2*)(gxr + g * H_DIM);
            acc[g][0] = v.x; acc[g][1] = v.y;
        }

        const float* hprev = (t & 1) ? hb1 : hb0;
        gemm_seg(acc, hprev, H_DIM, H_DIM, Whh, bt0, ht0, As0, Ws0, As1, Ws1);

        // gates
        {
            float i0, i1, f0, f1, q0, q1, o0, o1, cc0, cc1;
            unpack2(acc[0][0], i0, i1); unpack2(acc[1][0], f0, f1);
            unpack2(acc[2][0], q0, q1); unpack2(acc[3][0], o0, o1);
            unpack2(c01, cc0, cc1);
            cc0 = fast_sigmoid(f0) * cc0 + fast_sigmoid(i0) * fast_tanh(q0);
            cc1 = fast_sigmoid(f1) * cc1 + fast_sigmoid(i1) * fast_tanh(q1);
            c01 = pack2(cc0, cc1);
            hv01 = pack2(fast_sigmoid(o0) * fast_tanh(cc0),
                         fast_sigmoid(o1) * fast_tanh(cc1));
            unpack2(acc[0][1], i0, i1); unpack2(acc[1][1], f0, f1);
            unpack2(acc[2][1], q0, q1); unpack2(acc[3][1], o0, o1);
            unpack2(c23, cc0, cc1);
            cc0 = fast_sigmoid(f0) * cc0 + fast_sigmoid(i0) * fast_tanh(q0);
            cc1 = fast_sigmoid(f1) * cc1 + fast_sigmoid(i1) * fast_tanh(q1);
            c23 = pack2(cc0, cc1);
            hv23 = pack2(fast_sigmoid(o0) * fast_tanh(cc0),
                         fast_sigmoid(o1) * fast_tanh(cc1));
        }

        float* hnext = ((t + 1) & 1) ? hb1 : hb0;
        ulonglong2 hv; hv.x = hv01; hv.y = hv23;
        *(ulonglong2*)(hnext + oidx) = hv;
        *(ulonglong2*)(hstep + (size_t)t * B_DIM * H_DIM + oidx) = hv;

        gsync(genBase + (unsigned)t + 1u);
    }

    const size_t base = (size_t)S_LEN * B_DIM * H_DIM;
    const size_t BH = (size_t)B_DIM * H_DIM;
    ulonglong2 hv; hv.x = hv01; hv.y = hv23;
    ulonglong2 cv; cv.x = c01;  cv.y = c23;
    *(ulonglong2*)(out + base + (size_t)layer * BH + oidx) = hv;
    *(ulonglong2*)(out + base + (2 + (size_t)layer) * BH + oidx) = cv;
}

extern "C" void kernel_launch(void* const* d_in, const int* in_sizes, int n_in,
                              void* d_out, int out_size)
{
    const float* x    = (const float*)d_in[0];  // [S, B, IN]
    const float* br   = (const float*)d_in[1];  // [S, B, BR]
    const float* Wih0 = (const float*)d_in[2];  // [IN, 4H]
    const float* Wbh0 = (const float*)d_in[3];  // [BR, 4H]
    const float* Whh0 = (const float*)d_in[4];  // [H, 4H]
    const float* b0   = (const float*)d_in[5];  // [4H]
    const float* Wih1 = (const float*)d_in[6];  // [H, 4H]
    const float* Whh1 = (const float*)d_in[7];  // [H, 4H]
    const float* b1   = (const float*)d_in[8];  // [4H]
    float* out = (float*)d_out;

    init_kernel<<<(B_DIM * H_DIM + NTHREADS - 1) / NTHREADS, NTHREADS>>>();

    dim3 bulk_grid(G_DIM / 128, M_DIM / 32);   // (16, 4096)
    dim3 rec_grid(H_DIM / 32, B_DIM / 32);     // (16, 8) = 128 CTAs

    bulk0_kernel<<<bulk_grid, NTHREADS>>>(x, br, Wih0, Wbh0, b0);
    recur_kernel<<<rec_grid, NTHREADS>>>(0, Whh0, out);
    bulk1_kernel<<<bulk_grid, NTHREADS>>>(Wih1, b1);
    recur_kernel<<<rec_grid, NTHREADS>>>(1, Whh1, out);
}

// round 7
// speedup vs baseline: 3.6584x; 3.6584x over previous
#include <cuda_runtime.h>
#include <math.h>

typedef unsigned long long u64;
typedef unsigned int u32;

#define S_LEN 512
#define B_DIM 256
#define IN_DIM 256
#define BR_DIM 128
#define H_DIM 512
#define G_DIM 2048                 // 4*H
#define M_DIM (S_LEN * B_DIM)      // 131072
#define NCTAS 128

// ---------------- device scratch (no allocations allowed) ----------------
__device__ float g_gx[(size_t)M_DIM * G_DIM];           // input-side gate preacts (1 GiB)
__device__ float g_hs0[(size_t)S_LEN * B_DIM * H_DIM];  // layer-0 outputs
__device__ float g_h0[2][B_DIM * H_DIM];
__device__ float g_h1[2][B_DIM * H_DIM];
__device__ unsigned g_arrive;
__device__ volatile unsigned g_release;

// ---------------- packed f32x2 + activation helpers ----------------
__device__ __forceinline__ u64 pack2(float lo, float hi) {
    u64 r; asm("mov.b64 %0, {%1, %2};" : "=l"(r) : "f"(lo), "f"(hi)); return r;
}
__device__ __forceinline__ void unpack2(u64 v, float& lo, float& hi) {
    asm("mov.b64 {%0, %1}, %2;" : "=f"(lo), "=f"(hi) : "l"(v));
}
__device__ __forceinline__ void fma2(u64& d, u64 a, u64 b) {
    asm("fma.rn.f32x2 %0, %1, %2, %0;" : "+l"(d) : "l"(a), "l"(b));
}
__device__ __forceinline__ void add2(u64& d, u64 a) {
    asm("add.rn.f32x2 %0, %0, %1;" : "+l"(d) : "l"(a));
}
__device__ __forceinline__ float fast_sigmoid(float x) { return 1.0f / (1.0f + __expf(-x)); }
__device__ __forceinline__ float fast_tanh(float x) { return 1.0f - 2.0f / (__expf(2.0f * x) + 1.0f); }

// ---------------- cp.async ----------------
__device__ __forceinline__ u32 smem_u32(const void* p) {
    return (u32)__cvta_generic_to_shared(p);
}
#define CP16(d, s)  asm volatile("cp.async.cg.shared.global [%0], [%1], 16;" :: "r"(d), "l"(s))
#define CP4(d, s)   asm volatile("cp.async.ca.shared.global [%0], [%1], 4;"  :: "r"(d), "l"(s))
#define CPCOMMIT()  asm volatile("cp.async.commit_group;")
#define CPWAIT1()   asm volatile("cp.async.wait_group 1;")
#define CPWAIT0()   asm volatile("cp.async.wait_group 0;")

// ---------------- grid-wide sense barrier (128 co-resident CTAs) ----------------
__device__ __forceinline__ void gsync(unsigned gen) {
    __syncthreads();
    if (threadIdx.x == 0) {
        __threadfence();
        unsigned a = atomicAdd(&g_arrive, 1u);
        if (a == NCTAS - 1) {
            g_arrive = 0;
            __threadfence();
            g_release = gen;
        } else {
            while (g_release < gen) { }
            __threadfence();
        }
    }
    __syncthreads();
}

// ---------------- init ----------------
__global__ void __launch_bounds__(256, 1) init_kernel() {
    int i = blockIdx.x * blockDim.x + threadIdx.x;
    if (i == 0) { g_arrive = 0; g_release = 0; }
    if (i < B_DIM * H_DIM) {
        g_h0[0][i] = 0.0f;
        g_h1[0][i] = 0.0f;
    }
}

// =====================================================================
// BULK GEMM: 128x128 CTA tile, 256 threads, 8x8 micro-tile, KC=16,
// 3-stage cp.async pipeline. gx[m][n] += A[m][k] * W[k][n]
// Asm stage: [k][132] (m-major rows after 4B-cp transpose), Bsm: [k][132].
// =====================================================================
#define BKC 16
#define BST (BKC * 132)   // floats per stage per operand

template <int NC>
__device__ __forceinline__ void bulk_seg(
    u64 acc[8][4], const float* __restrict__ A, int ldA,
    const float* __restrict__ W, int mBase, int nBase,
    float* Asm, float* Bsm)
{
    const int tid = threadIdx.x;
    const int tx = tid & 15, ty = tid >> 4;

    u32 asb[3], bsb[3];
    #pragma unroll
    for (int s = 0; s < 3; s++) {
        asb[s] = smem_u32(Asm + s * BST);
        bsb[s] = smem_u32(Bsm + s * BST);
    }

    auto issue = [&](int c) {
        int s = c % 3;
        // B tile: 16 k-rows x 128 cols, contiguous 16B chunks
        #pragma unroll
        for (int e = 0; e < 2; e++) {
            int id = tid + 256 * e;
            int k = id >> 5, s32 = id & 31;
            const float* src = W + (size_t)(c * BKC + k) * G_DIM + nBase + s32 * 4;
            CP16(bsb[s] + (u32)(k * 132 + s32 * 4) * 4, src);
        }
        // A tile: 128 rows x 16 k, transposed via 4B copies
        #pragma unroll
        for (int e = 0; e < 8; e++) {
            int id = tid + 256 * e;
            int k = id & 15, r = id >> 4;
            const float* src = A + (size_t)(mBase + r) * ldA + c * BKC + k;
            CP4(asb[s] + (u32)(k * 132 + r) * 4, src);
        }
        CPCOMMIT();
    };

    issue(0); issue(1);
    CPWAIT1(); __syncthreads();

    #pragma unroll 1
    for (int c = 0; c < NC; c++) {
        if (c + 2 < NC) issue(c + 2);
        const float* Ap = Asm + (c % 3) * BST;
        const float* Bp = Bsm + (c % 3) * BST;
        #pragma unroll
        for (int k = 0; k < BKC; k++) {
            float4 a0 = *(const float4*)(Ap + k * 132 + ty * 8);
            float4 a1 = *(const float4*)(Ap + k * 132 + ty * 8 + 4);
            float4 b0 = *(const float4*)(Bp + k * 132 + tx * 8);
            float4 b1 = *(const float4*)(Bp + k * 132 + tx * 8 + 4);
            u64 w[4] = { pack2(b0.x, b0.y), pack2(b0.z, b0.w),
                         pack2(b1.x, b1.y), pack2(b1.z, b1.w) };
            float am[8] = { a0.x, a0.y, a0.z, a0.w, a1.x, a1.y, a1.z, a1.w };
            #pragma unroll
            for (int m = 0; m < 8; m++) {
                u64 aa = pack2(am[m], am[m]);
                #pragma unroll
                for (int np = 0; np < 4; np++) fma2(acc[m][np], w[np], aa);
            }
        }
        if (c + 2 < NC) { CPWAIT1(); } else { CPWAIT0(); }
        __syncthreads();
    }
}

__device__ __forceinline__ void bulk_epilogue(
    u64 acc[8][4], const float* __restrict__ bias, int mBase, int nBase)
{
    const int tid = threadIdx.x;
    const int tx = tid & 15, ty = tid >> 4;
    float4 bb0 = *(const float4*)(bias + nBase + tx * 8);
    float4 bb1 = *(const float4*)(bias + nBase + tx * 8 + 4);
    u64 bp[4] = { pack2(bb0.x, bb0.y), pack2(bb0.z, bb0.w),
                  pack2(bb1.x, bb1.y), pack2(bb1.z, bb1.w) };
    #pragma unroll
    for (int m = 0; m < 8; m++) {
        u64 r0 = acc[m][0], r1 = acc[m][1], r2 = acc[m][2], r3 = acc[m][3];
        add2(r0, bp[0]); add2(r1, bp[1]); add2(r2, bp[2]); add2(r3, bp[3]);
        float* dst = g_gx + (size_t)(mBase + ty * 8 + m) * G_DIM + nBase + tx * 8;
        ulonglong2 v0; v0.x = r0; v0.y = r1;
        ulonglong2 v1; v1.x = r2; v1.y = r3;
        ((ulonglong2*)dst)[0] = v0;
        ((ulonglong2*)dst)[1] = v1;
    }
}

// layer0: gx = bias0 + x@Wih0 + b@Wbh0
__global__ void __launch_bounds__(256, 2) bulk0_kernel(
    const float* __restrict__ x, const float* __restrict__ br,
    const float* __restrict__ Wih, const float* __restrict__ Wbh,
    const float* __restrict__ bias)
{
    extern __shared__ __align__(16) float sm[];
    float* Asm = sm;
    float* Bsm = sm + 3 * BST;
    const int nBase = blockIdx.x * 128;
    const int mBase = blockIdx.y * 128;

    u64 acc[8][4] = {};
    bulk_seg<IN_DIM / BKC>(acc, x, IN_DIM, Wih, mBase, nBase, Asm, Bsm);
    bulk_seg<BR_DIM / BKC>(acc, br, BR_DIM, Wbh, mBase, nBase, Asm, Bsm);
    bulk_epilogue(acc, bias, mBase, nBase);
}

// layer1: gx = bias1 + hs0@Wih1
__global__ void __launch_bounds__(256, 2) bulk1_kernel(
    const float* __restrict__ Wih, const float* __restrict__ bias)
{
    extern __shared__ __align__(16) float sm[];
    float* Asm = sm;
    float* Bsm = sm + 3 * BST;
    const int nBase = blockIdx.x * 128;
    const int mBase = blockIdx.y * 128;

    u64 acc[8][4] = {};
    bulk_seg<H_DIM / BKC>(acc, g_hs0, H_DIM, Wih, mBase, nBase, Asm, Bsm);
    bulk_epilogue(acc, bias, mBase, nBase);
}

// =====================================================================
// RECURRENT persistent kernel (one launch per layer).
// CTA tile: 32b x 128 gate-cols (32h x 4 gates). 256 threads.
// Thread (bq,hq,g): 4b x 4h of one gate -> 2 LDS.128 per k, 8 FFMA2.
// Gates re-gathered per (b,h) via smem exchange; c-state in registers.
// Stages: Wsm[3][32*132] ([k][g*32+h]), Asm[3][32*36] ([k][b], pad 36
// keeps LDS.128 alignment). Gsm[4][32*33] exchange.
// =====================================================================
#define RKC 32
#define RWST (RKC * 132)
#define RAST (RKC * 36)
#define RNC (H_DIM / RKC)   // 16

__global__ void __launch_bounds__(256, 1) recur_kernel(
    int layer, const float* __restrict__ Whh, float* __restrict__ out)
{
    extern __shared__ __align__(16) float sm[];
    float* Wsm = sm;                       // 3 * 4224
    float* Asm = sm + 3 * RWST;            // 3 * 1152
    float* Gsm = Asm + 3 * RAST;           // 4 * 1056

    const int tid = threadIdx.x;
    const int bq = tid & 7;                // b = 4*bq + i
    const int hq = (tid >> 3) & 7;         // h = 4*hq + j
    const int g  = tid >> 6;               // gate
    const int ht0 = blockIdx.x * 32;       // gridDim.x = 16
    const int bt0 = blockIdx.y * 32;       // gridDim.y = 8

    float* hb0 = (layer == 0) ? g_h0[0] : g_h1[0];
    float* hb1 = (layer == 0) ? g_h0[1] : g_h1[1];
    float* hstep = (layer == 0) ? g_hs0 : out;
    const unsigned genBase = (layer == 0) ? 0u : (unsigned)S_LEN;

    const int cellb = tid >> 3;            // 0..31 (epilogue cell ownership)
    const int cellh = (tid & 7) * 4;

    u32 wsb[3], asb[3];
    #pragma unroll
    for (int s = 0; s < 3; s++) {
        wsb[s] = smem_u32(Wsm + s * RWST);
        asb[s] = smem_u32(Asm + s * RAST);
    }

    float cst[4] = {0.f, 0.f, 0.f, 0.f};
    float hfin[4] = {0.f, 0.f, 0.f, 0.f};

    for (int t = 0; t < S_LEN; t++) {
        const float* A = (t & 1) ? hb1 : hb0;

        auto issue = [&](int c) {
            int s = c % 3;
            #pragma unroll
            for (int e = 0; e < 4; e++) {
                int id = tid + 256 * e;
                int k = id >> 5, q = id & 31;
                const float* src = Whh + (size_t)(c * RKC + k) * G_DIM
                                   + (q >> 3) * H_DIM + ht0 + (q & 7) * 4;
                CP16(wsb[s] + (u32)(k * 132 + q * 4) * 4, src);
            }
            #pragma unroll
            for (int e = 0; e < 4; e++) {
                int id = tid + 256 * e;
                int k = id & 31, b = id >> 5;
                const float* src = A + (size_t)(bt0 + b) * H_DIM + c * RKC + k;
                CP4(asb[s] + (u32)(k * 36 + b) * 4, src);
            }
            CPCOMMIT();
        };

        u64 acc[4][2] = {};
        issue(0); issue(1);
        CPWAIT1(); __syncthreads();

        #pragma unroll 1
        for (int c = 0; c < RNC; c++) {
            if (c + 2 < RNC) issue(c + 2);
            const float* Ap = Asm + (c % 3) * RAST;
            const float* Wp = Wsm + (c % 3) * RWST;
            #pragma unroll
            for (int k = 0; k < RKC; k++) {
                float4 av = *(const float4*)(Ap + k * 36 + 4 * bq);
                float4 wv = *(const float4*)(Wp + k * 132 + g * 32 + 4 * hq);
                u64 w01 = pack2(wv.x, wv.y);
                u64 w23 = pack2(wv.z, wv.w);
                float am[4] = { av.x, av.y, av.z, av.w };
                #pragma unroll
                for (int i = 0; i < 4; i++) {
                    u64 aa = pack2(am[i], am[i]);
                    fma2(acc[i][0], w01, aa);
                    fma2(acc[i][1], w23, aa);
                }
            }
            if (c + 2 < RNC) { CPWAIT1(); } else { CPWAIT0(); }
            __syncthreads();
        }

        // add input-side preacts (gx) into acc
        const float* gxr = g_gx + ((size_t)t * B_DIM + bt0 + 4 * bq) * G_DIM
                           + g * H_DIM + ht0 + 4 * hq;
        #pragma unroll
        for (int i = 0; i < 4; i++) {
            float4 v = *(const float4*)(gxr + (size_t)i * G_DIM);
            add2(acc[i][0], pack2(v.x, v.y));
            add2(acc[i][1], pack2(v.z, v.w));
        }

        // gate exchange: Gsm[g][h][b] (pad b to 33)
        float* Gg = Gsm + g * (32 * 33);
        #pragma unroll
        for (int i = 0; i < 4; i++) {
            float f0, f1, f2, f3;
            unpack2(acc[i][0], f0, f1);
            unpack2(acc[i][1], f2, f3);
            Gg[(4 * hq + 0) * 33 + 4 * bq + i] = f0;
            Gg[(4 * hq + 1) * 33 + 4 * bq + i] = f1;
            Gg[(4 * hq + 2) * 33 + 4 * bq + i] = f2;
            Gg[(4 * hq + 3) * 33 + 4 * bq + i] = f3;
        }
        __syncthreads();

        // per-cell LSTM update (cell = (cellb, cellh+j)), c-state in regs
        #pragma unroll
        for (int j = 0; j < 4; j++) {
            int h = cellh + j;
            float iv = Gsm[0 * 1056 + h * 33 + cellb];
            float fv = Gsm[1 * 1056 + h * 33 + cellb];
            float gv = Gsm[2 * 1056 + h * 33 + cellb];
            float ov = Gsm[3 * 1056 + h * 33 + cellb];
            float c_ = fast_sigmoid(fv) * cst[j] + fast_sigmoid(iv) * fast_tanh(gv);
            cst[j] = c_;
            hfin[j] = fast_sigmoid(ov) * fast_tanh(c_);
        }

        float* hnext = ((t + 1) & 1) ? hb1 : hb0;
        size_t oidx = (size_t)(bt0 + cellb) * H_DIM + ht0 + cellh;
        ulonglong2 hv;
        hv.x = pack2(hfin[0], hfin[1]);
        hv.y = pack2(hfin[2], hfin[3]);
        *(ulonglong2*)(hnext + oidx) = hv;
        *(ulonglong2*)(hstep + (size_t)t * B_DIM * H_DIM + oidx) = hv;

        gsync(genBase + (unsigned)t + 1u);
    }

    const size_t base = (size_t)S_LEN * B_DIM * H_DIM;
    const size_t BH = (size_t)B_DIM * H_DIM;
    size_t oidx = (size_t)(bt0 + cellb) * H_DIM + ht0 + cellh;
    ulonglong2 hv;
    hv.x = pack2(hfin[0], hfin[1]);
    hv.y = pack2(hfin[2], hfin[3]);
    ulonglong2 cv;
    cv.x = pack2(cst[0], cst[1]);
    cv.y = pack2(cst[2], cst[3]);
    *(ulonglong2*)(out + base + (size_t)layer * BH + oidx) = hv;
    *(ulonglong2*)(out + base + (2 + (size_t)layer) * BH + oidx) = cv;
}

// =====================================================================
extern "C" void kernel_launch(void* const* d_in, const int* in_sizes, int n_in,
                              void* d_out, int out_size)
{
    const float* x    = (const float*)d_in[0];  // [S, B, IN]
    const float* br   = (const float*)d_in[1];  // [S, B, BR]
    const float* Wih0 = (const float*)d_in[2];  // [IN, 4H]
    const float* Wbh0 = (const float*)d_in[3];  // [BR, 4H]
    const float* Whh0 = (const float*)d_in[4];  // [H, 4H]
    const float* b0   = (const float*)d_in[5];  // [4H]
    const float* Wih1 = (const float*)d_in[6];  // [H, 4H]
    const float* Whh1 = (const float*)d_in[7];  // [H, 4H]
    const float* b1   = (const float*)d_in[8];  // [4H]
    float* out = (float*)d_out;

    const int bulk_smem = 3 * BST * 2 * sizeof(float);                     // 50688
    const int recur_smem = 120 * 1024;  // oversized to pin 1 CTA/SM (need 81408)

    cudaFuncSetAttribute(bulk0_kernel, cudaFuncAttributeMaxDynamicSharedMemorySize, bulk_smem);
    cudaFuncSetAttribute(bulk1_kernel, cudaFuncAttributeMaxDynamicSharedMemorySize, bulk_smem);
    cudaFuncSetAttribute(recur_kernel, cudaFuncAttributeMaxDynamicSharedMemorySize, recur_smem);

    init_kernel<<<(B_DIM * H_DIM + 255) / 256, 256>>>();

    dim3 bulk_grid(G_DIM / 128, M_DIM / 128);  // (16, 1024)
    dim3 rec_grid(H_DIM / 32, B_DIM / 32);     // (16, 8) = 128 CTAs

    bulk0_kernel<<<bulk_grid, 256, bulk_smem>>>(x, br, Wih0, Wbh0, b0);
    recur_kernel<<<rec_grid, 256, recur_smem>>>(0, Whh0, out);
    bulk1_kernel<<<bulk_grid, 256, bulk_smem>>>(Wih1, b1);
    recur_kernel<<<rec_grid, 256, recur_smem>>>(1, Whh1, out);
}

// round 9
// speedup vs baseline: 4.2297x; 1.1562x over previous
#include <cuda_runtime.h>
#include <math.h>

typedef unsigned long long u64;
typedef unsigned int u32;

#define S_LEN 512
#define B_DIM 256
#define IN_DIM 256
#define BR_DIM 128
#define H_DIM 512
#define G_DIM 2048                 // 4*H
#define M_DIM (S_LEN * B_DIM)      // 131072

// ---------------- device scratch (no allocations allowed) ----------------
// gx layout: [(t*4+g)][h:512][b:256]  (transposed, 1 GiB)
__device__ float g_gx[(size_t)M_DIM * G_DIM];
// hs0 layout: [t][h:512][b:256]  (transposed, 256 MiB) -- doubles as layer-0 h history
__device__ float g_hs0[(size_t)S_LEN * H_DIM * B_DIM];
__device__ float g_h1t[2][H_DIM * B_DIM];               // layer-1 h double buffer, [h][b]
__device__ unsigned g_grp[8];
__device__ unsigned g_root;
__device__ volatile unsigned g_release;

// ---------------- packed f32x2 + activation helpers ----------------
__device__ __forceinline__ u64 pack2(float lo, float hi) {
    u64 r; asm("mov.b64 %0, {%1, %2};" : "=l"(r) : "f"(lo), "f"(hi)); return r;
}
__device__ __forceinline__ void unpack2(u64 v, float& lo, float& hi) {
    asm("mov.b64 {%0, %1}, %2;" : "=f"(lo), "=f"(hi) : "l"(v));
}
__device__ __forceinline__ void fma2(u64& d, u64 a, u64 b) {
    asm("fma.rn.f32x2 %0, %1, %2, %0;" : "+l"(d) : "l"(a), "l"(b));
}
__device__ __forceinline__ void add2(u64& d, u64 a) {
    asm("add.rn.f32x2 %0, %0, %1;" : "+l"(d) : "l"(a));
}
__device__ __forceinline__ float fast_sigmoid(float x) { return 1.0f / (1.0f + __expf(-x)); }
__device__ __forceinline__ float fast_tanh(float x) { return 1.0f - 2.0f / (__expf(2.0f * x) + 1.0f); }

// ---------------- cp.async ----------------
__device__ __forceinline__ u32 smem_u32(const void* p) {
    return (u32)__cvta_generic_to_shared(p);
}
#define CP16(d, s)  asm volatile("cp.async.cg.shared.global [%0], [%1], 16;" :: "r"(d), "l"(s))
#define CP4(d, s)   asm volatile("cp.async.ca.shared.global [%0], [%1], 4;"  :: "r"(d), "l"(s))
#define CPCOMMIT()  asm volatile("cp.async.commit_group;")
#define CPWAIT1()   asm volatile("cp.async.wait_group 1;")
#define CPWAIT0()   asm volatile("cp.async.wait_group 0;")

// ---------------- two-level grid barrier (128 co-resident CTAs) ----------------
__device__ __forceinline__ void gsync(int bid, unsigned gen) {
    __syncthreads();
    if (threadIdx.x == 0) {
        __threadfence();
        unsigned a = atomicAdd(&g_grp[bid >> 4], 1u);
        if (a == 15u) {
            unsigned r = atomicAdd(&g_root, 1u);
            if (r == 7u) {
                g_root = 0;
                #pragma unroll
                for (int i = 0; i < 8; i++) g_grp[i] = 0;
                __threadfence();
                g_release = gen;
            }
        }
        while (g_release < gen) { }
        __threadfence();
    }
    __syncthreads();
}

// ---------------- init ----------------
__global__ void __launch_bounds__(64, 1) init_kernel() {
    if (threadIdx.x == 0 && blockIdx.x == 0) {
        #pragma unroll
        for (int i = 0; i < 8; i++) g_grp[i] = 0;
        g_root = 0;
        g_release = 0;
    }
}

// =====================================================================
// BULK GEMM: 128x128 CTA tile, 256 threads, 8x8 micro-tile, KC=16,
// 3-stage cp.async pipeline. Epilogue writes gx TRANSPOSED [t4g][h][b].
// =====================================================================
#define BKC 16
#define BST (BKC * 132)   // floats per stage per operand

template <int NC>
__device__ __forceinline__ void bulk_seg(
    u64 acc[8][4], const float* __restrict__ A, int ldA,
    const float* __restrict__ W, int mBase, int nBase,
    float* Asm, float* Bsm)
{
    const int tid = threadIdx.x;
    const int tx = tid & 15, ty = tid >> 4;

    u32 asb[3], bsb[3];
    #pragma unroll
    for (int s = 0; s < 3; s++) {
        asb[s] = smem_u32(Asm + s * BST);
        bsb[s] = smem_u32(Bsm + s * BST);
    }

    auto issue = [&](int c) {
        int s = c % 3;
        #pragma unroll
        for (int e = 0; e < 2; e++) {
            int id = tid + 256 * e;
            int k = id >> 5, s32 = id & 31;
            const float* src = W + (size_t)(c * BKC + k) * G_DIM + nBase + s32 * 4;
            CP16(bsb[s] + (u32)(k * 132 + s32 * 4) * 4, src);
        }
        #pragma unroll
        for (int e = 0; e < 8; e++) {
            int id = tid + 256 * e;
            int k = id & 15, r = id >> 4;
            const float* src = A + (size_t)(mBase + r) * ldA + c * BKC + k;
            CP4(asb[s] + (u32)(k * 132 + r) * 4, src);
        }
        CPCOMMIT();
    };

    issue(0); issue(1);
    CPWAIT1(); __syncthreads();

    #pragma unroll 1
    for (int c = 0; c < NC; c++) {
        if (c + 2 < NC) issue(c + 2);
        const float* Ap = Asm + (c % 3) * BST;
        const float* Bp = Bsm + (c % 3) * BST;
        #pragma unroll
        for (int k = 0; k < BKC; k++) {
            float4 a0 = *(const float4*)(Ap + k * 132 + ty * 8);
            float4 a1 = *(const float4*)(Ap + k * 132 + ty * 8 + 4);
            float4 b0 = *(const float4*)(Bp + k * 132 + tx * 8);
            float4 b1 = *(const float4*)(Bp + k * 132 + tx * 8 + 4);
            u64 w[4] = { pack2(b0.x, b0.y), pack2(b0.z, b0.w),
                         pack2(b1.x, b1.y), pack2(b1.z, b1.w) };
            float am[8] = { a0.x, a0.y, a0.z, a0.w, a1.x, a1.y, a1.z, a1.w };
            #pragma unroll
            for (int m = 0; m < 8; m++) {
                u64 aa = pack2(am[m], am[m]);
                #pragma unroll
                for (int np = 0; np < 4; np++) fma2(acc[m][np], w[np], aa);
            }
        }
        if (c + 2 < NC) { CPWAIT1(); } else { CPWAIT0(); }
        __syncthreads();
    }
}

// Writes gx transposed: gx[(t*4+g)][h][b] = acc + bias
__device__ __forceinline__ void bulk_epilogue(
    u64 acc[8][4], const float* __restrict__ bias, int mBase, int nBase)
{
    const int tid = threadIdx.x;
    const int tx = tid & 15, ty = tid >> 4;
    const int t = mBase >> 8;
    const int b0 = (mBase & 255) + ty * 8;

    float4 bb0 = *(const float4*)(bias + nBase + tx * 8);
    float4 bb1 = *(const float4*)(bias + nBase + tx * 8 + 4);
    float bcol[8] = { bb0.x, bb0.y, bb0.z, bb0.w, bb1.x, bb1.y, bb1.z, bb1.w };

    float f[8][8];
    #pragma unroll
    for (int m = 0; m < 8; m++) {
        #pragma unroll
        for (int np = 0; np < 4; np++) {
            float lo, hi;
            unpack2(acc[m][np], lo, hi);
            f[m][2 * np]     = lo + bcol[2 * np];
            f[m][2 * np + 1] = hi + bcol[2 * np + 1];
        }
    }
    #pragma unroll
    for (int nn = 0; nn < 8; nn++) {
        int n = nBase + tx * 8 + nn;
        int g = n >> 9, h = n & 511;
        float* dst = g_gx + (((size_t)(t * 4 + g)) * H_DIM + h) * B_DIM + b0;
        float4 v0 = make_float4(f[0][nn], f[1][nn], f[2][nn], f[3][nn]);
        float4 v1 = make_float4(f[4][nn], f[5][nn], f[6][nn], f[7][nn]);
        *(float4*)dst = v0;
        *(float4*)(dst + 4) = v1;
    }
}

// layer0: gx = bias0 + x@Wih0 + b@Wbh0
__global__ void __launch_bounds__(256, 2) bulk0_kernel(
    const float* __restrict__ x, const float* __restrict__ br,
    const float* __restrict__ Wih, const float* __restrict__ Wbh,
    const float* __restrict__ bias)
{
    extern __shared__ __align__(16) float sm[];
    float* Asm = sm;
    float* Bsm = sm + 3 * BST;
    const int nBase = blockIdx.x * 128;
    const int mBase = blockIdx.y * 128;

    u64 acc[8][4] = {};
    bulk_seg<IN_DIM / BKC>(acc, x, IN_DIM, Wih, mBase, nBase, Asm, Bsm);
    bulk_seg<BR_DIM / BKC>(acc, br, BR_DIM, Wbh, mBase, nBase, Asm, Bsm);
    bulk_epilogue(acc, bias, mBase, nBase);
}

// layer1: gx = bias1 + hs0@Wih1, with hs0 stored transposed [t][h][b]
__global__ void __launch_bounds__(256, 2) bulk1_kernel(
    const float* __restrict__ Wih, const float* __restrict__ bias)
{
    extern __shared__ __align__(16) float sm[];
    float* Asm = sm;
    float* Bsm = sm + 3 * BST;
    const int tid = threadIdx.x;
    const int nBase = blockIdx.x * 128;
    const int mBase = blockIdx.y * 128;
    const int t = mBase >> 8;
    const int bo = mBase & 255;

    u32 asb[3], bsb[3];
    #pragma unroll
    for (int s = 0; s < 3; s++) {
        asb[s] = smem_u32(Asm + s * BST);
        bsb[s] = smem_u32(Bsm + s * BST);
    }

    auto issue = [&](int c) {
        int s = c % 3;
        #pragma unroll
        for (int e = 0; e < 2; e++) {
            int id = tid + 256 * e;
            int k = id >> 5, s32 = id & 31;
            const float* src = Wih + (size_t)(c * BKC + k) * G_DIM + nBase + s32 * 4;
            CP16(bsb[s] + (u32)(k * 132 + s32 * 4) * 4, src);
        }
        // A from g_hs0[t][k][b] : k-major rows, CP16, no transpose
        #pragma unroll
        for (int e = 0; e < 2; e++) {
            int id = tid + 256 * e;
            int k = id >> 5, seg = id & 31;
            const float* src = g_hs0 + ((size_t)t * H_DIM + c * BKC + k) * B_DIM + bo + seg * 4;
            CP16(asb[s] + (u32)(k * 132 + seg * 4) * 4, src);
        }
        CPCOMMIT();
    };

    u64 acc[8][4] = {};
    issue(0); issue(1);
    CPWAIT1(); __syncthreads();

    const int tx = tid & 15, ty = tid >> 4;
    #pragma unroll 1
    for (int c = 0; c < H_DIM / BKC; c++) {
        if (c + 2 < H_DIM / BKC) issue(c + 2);
        const float* Ap = Asm + (c % 3) * BST;
        const float* Bp = Bsm + (c % 3) * BST;
        #pragma unroll
        for (int k = 0; k < BKC; k++) {
            float4 a0 = *(const float4*)(Ap + k * 132 + ty * 8);
            float4 a1 = *(const float4*)(Ap + k * 132 + ty * 8 + 4);
            float4 b0 = *(const float4*)(Bp + k * 132 + tx * 8);
            float4 b1 = *(const float4*)(Bp + k * 132 + tx * 8 + 4);
            u64 w[4] = { pack2(b0.x, b0.y), pack2(b0.z, b0.w),
                         pack2(b1.x, b1.y), pack2(b1.z, b1.w) };
            float am[8] = { a0.x, a0.y, a0.z, a0.w, a1.x, a1.y, a1.z, a1.w };
            #pragma unroll
            for (int m = 0; m < 8; m++) {
                u64 aa = pack2(am[m], am[m]);
                #pragma unroll
                for (int np = 0; np < 4; np++) fma2(acc[m][np], w[np], aa);
            }
        }
        if (c + 2 < H_DIM / BKC) { CPWAIT1(); } else { CPWAIT0(); }
        __syncthreads();
    }
    bulk_epilogue(acc, bias, mBase, nBase);
}

// =====================================================================
// RECURRENT persistent kernel. Grid: 32 h-CTAs (16 h each, all 4 gates)
// x 4 b-CTAs (64 b). 128 threads: thread (bq 0..15, hp 0..7) owns
// 4b x 2h x 4gates = 16 u64 accs. W (512k x 64 cols) persistent in smem
// [k][g][h16] (128 KB). A streamed [k][b] via CP16, 8 chunks of 64k,
// 3-stage pipeline. gx prefetched via 8 LDG.128. c-state in registers.
// =====================================================================
#define RKC 64
#define RAST (RKC * 68)          // A stage floats (pad 68 keeps 16B align)
#define RW_FLOATS (H_DIM * 64)   // 32768 floats = 128 KB

__global__ void __launch_bounds__(128, 1) recur_kernel(
    int layer, const float* __restrict__ Whh, float* __restrict__ out)
{
    extern __shared__ __align__(16) float sm[];
    float* Wsm = sm;                    // [k512][g4][h16]
    float* Asm = sm + RW_FLOATS;        // 3 stages of [k64][68]

    const int tid = threadIdx.x;
    const int bq = tid & 15;            // b = bt0 + 4*bq + {0..3}
    const int hp = tid >> 4;            // h = ht0 + 2*hp + {0,1}
    const int ht0 = blockIdx.x * 16;    // gridDim.x = 32
    const int bt0 = blockIdx.y * 64;    // gridDim.y = 4
    const int bid = blockIdx.y * 32 + blockIdx.x;
    const unsigned genBase = (layer == 0) ? 0u : (unsigned)S_LEN;

    u32 wsb = smem_u32(Wsm);
    u32 asb[3];
    #pragma unroll
    for (int s = 0; s < 3; s++) asb[s] = smem_u32(Asm + s * RAST);

    // ---- load W once: Whh[k][g*512 + ht0 + h], dst [k][g*16 + h] ----
    #pragma unroll 8
    for (int e = 0; e < 64; e++) {
        int id = tid + 128 * e;
        int k = id >> 4, q = id & 15;   // q: g = q>>2, hquad = q&3
        const float* src = Whh + (size_t)k * G_DIM + (q >> 2) * H_DIM + ht0 + (q & 3) * 4;
        CP16(wsb + (u32)(k * 64 + q * 4) * 4, src);
    }
    CPCOMMIT(); CPWAIT0(); __syncthreads();

    float cst[4][2] = {};
    float hfin[4][2] = {};

    for (int t = 0; t < S_LEN; t++) {
        // ---- gx prefetch: gx[(t*4+g)][ht0+2hp+hh][bt0+4bq..] ----
        float4 gxv[8];
        const float* gxb = g_gx + (size_t)t * 4 * H_DIM * B_DIM;
        #pragma unroll
        for (int g = 0; g < 4; g++) {
            #pragma unroll
            for (int hh = 0; hh < 2; hh++) {
                gxv[g * 2 + hh] = *(const float4*)(
                    gxb + ((size_t)g * H_DIM + ht0 + 2 * hp + hh) * B_DIM + bt0 + 4 * bq);
            }
        }

        u64 acc[4][4];  // [b][gate], pair over (h0,h1)
        #pragma unroll
        for (int g = 0; g < 4; g++) {
            float* lo = (float*)&gxv[g * 2];
            float* hi = (float*)&gxv[g * 2 + 1];
            #pragma unroll
            for (int b = 0; b < 4; b++) acc[b][g] = pack2(lo[b], hi[b]);
        }

        if (t > 0) {
            const float* Asrc = (layer == 0)
                ? g_hs0 + (size_t)(t - 1) * H_DIM * B_DIM
                : g_h1t[t & 1];

            auto issueA = [&](int c) {
                int s = c % 3;
                #pragma unroll
                for (int e = 0; e < 8; e++) {
                    int id = tid + 128 * e;
                    int k = id >> 4, seg = id & 15;
                    const float* src = Asrc + (size_t)(c * RKC + k) * B_DIM + bt0 + seg * 4;
                    CP16(asb[s] + (u32)(k * 68 + seg * 4) * 4, src);
                }
                CPCOMMIT();
            };

            issueA(0); issueA(1);
            CPWAIT1(); __syncthreads();

            #pragma unroll 1
            for (int c = 0; c < 8; c++) {
                if (c < 6) issueA(c + 2);
                const float* Ap = Asm + (c % 3) * RAST;
                const float* Wp = Wsm + c * (RKC * 64);
                #pragma unroll 8
                for (int k = 0; k < RKC; k++) {
                    float4 av = *(const float4*)(Ap + k * 68 + 4 * bq);
                    u64 w0 = *(const u64*)(Wp + k * 64 +  0 + 2 * hp);
                    u64 w1 = *(const u64*)(Wp + k * 64 + 16 + 2 * hp);
                    u64 w2 = *(const u64*)(Wp + k * 64 + 32 + 2 * hp);
                    u64 w3 = *(const u64*)(Wp + k * 64 + 48 + 2 * hp);
                    float am[4] = { av.x, av.y, av.z, av.w };
                    #pragma unroll
                    for (int b = 0; b < 4; b++) {
                        u64 aa = pack2(am[b], am[b]);
                        fma2(acc[b][0], w0, aa);
                        fma2(acc[b][1], w1, aa);
                        fma2(acc[b][2], w2, aa);
                        fma2(acc[b][3], w3, aa);
                    }
                }
                if (c < 6) { CPWAIT1(); } else { CPWAIT0(); }
                __syncthreads();
            }
        }

        // ---- gates ----
        #pragma unroll
        for (int b = 0; b < 4; b++) {
            float i0, i1, f0, f1, q0, q1, o0, o1;
            unpack2(acc[b][0], i0, i1);
            unpack2(acc[b][1], f0, f1);
            unpack2(acc[b][2], q0, q1);
            unpack2(acc[b][3], o0, o1);
            float c0 = fast_sigmoid(f0) * cst[b][0] + fast_sigmoid(i0) * fast_tanh(q0);
            float c1 = fast_sigmoid(f1) * cst[b][1] + fast_sigmoid(i1) * fast_tanh(q1);
            cst[b][0] = c0; cst[b][1] = c1;
            hfin[b][0] = fast_sigmoid(o0) * fast_tanh(c0);
            hfin[b][1] = fast_sigmoid(o1) * fast_tanh(c1);
        }

        // ---- stores ----
        if (layer == 0) {
            #pragma unroll
            for (int hh = 0; hh < 2; hh++) {
                float4 v = make_float4(hfin[0][hh], hfin[1][hh], hfin[2][hh], hfin[3][hh]);
                *(float4*)(g_hs0 + ((size_t)t * H_DIM + ht0 + 2 * hp + hh) * B_DIM
                           + bt0 + 4 * bq) = v;
            }
        } else {
            float* hb = g_h1t[(t + 1) & 1];
            #pragma unroll
            for (int hh = 0; hh < 2; hh++) {
                float4 v = make_float4(hfin[0][hh], hfin[1][hh], hfin[2][hh], hfin[3][hh]);
                *(float4*)(hb + ((size_t)(ht0 + 2 * hp + hh)) * B_DIM + bt0 + 4 * bq) = v;
            }
            #pragma unroll
            for (int b = 0; b < 4; b++) {
                *(float2*)(out + ((size_t)t * B_DIM + bt0 + 4 * bq + b) * H_DIM
                           + ht0 + 2 * hp) = make_float2(hfin[b][0], hfin[b][1]);
            }
        }

        gsync(bid, genBase + (unsigned)t + 1u);
    }

    // ---- finals: h_n, c_n ----
    const size_t base = (size_t)S_LEN * B_DIM * H_DIM;
    const size_t BH = (size_t)B_DIM * H_DIM;
    #pragma unroll
    for (int b = 0; b < 4; b++) {
        size_t row = (size_t)(bt0 + 4 * bq + b) * H_DIM + ht0 + 2 * hp;
        *(float2*)(out + base + (size_t)layer * BH + row) =
            make_float2(hfin[b][0], hfin[b][1]);
        *(float2*)(out + base + (2 + (size_t)layer) * BH + row) =
            make_float2(cst[b][0], cst[b][1]);
    }
}

// =====================================================================
extern "C" void kernel_launch(void* const* d_in, const int* in_sizes, int n_in,
                              void* d_out, int out_size)
{
    const float* x    = (const float*)d_in[0];  // [S, B, IN]
    const float* br   = (const float*)d_in[1];  // [S, B, BR]
    const float* Wih0 = (const float*)d_in[2];  // [IN, 4H]
    const float* Wbh0 = (const float*)d_in[3];  // [BR, 4H]
    const float* Whh0 = (const float*)d_in[4];  // [H, 4H]
    const float* b0   = (const float*)d_in[5];  // [4H]
    const float* Wih1 = (const float*)d_in[6];  // [H, 4H]
    const float* Whh1 = (const float*)d_in[7];  // [H, 4H]
    const float* b1   = (const float*)d_in[8];  // [4H]
    float* out = (float*)d_out;

    const int bulk_smem  = 3 * BST * 2 * sizeof(float);            // 50688
    const int recur_smem = (RW_FLOATS + 3 * RAST) * sizeof(float); // 183296

    cudaFuncSetAttribute(bulk0_kernel, cudaFuncAttributeMaxDynamicSharedMemorySize, bulk_smem);
    cudaFuncSetAttribute(bulk1_kernel, cudaFuncAttributeMaxDynamicSharedMemorySize, bulk_smem);
    cudaFuncSetAttribute(recur_kernel, cudaFuncAttributeMaxDynamicSharedMemorySize, recur_smem);

    init_kernel<<<1, 64>>>();

    dim3 bulk_grid(G_DIM / 128, M_DIM / 128);  // (16, 1024)
    dim3 rec_grid(H_DIM / 16, B_DIM / 64);     // (32, 4) = 128 CTAs

    bulk0_kernel<<<bulk_grid, 256, bulk_smem>>>(x, br, Wih0, Wbh0, b0);
    recur_kernel<<<rec_grid, 128, recur_smem>>>(0, Whh0, out);
    bulk1_kernel<<<bulk_grid, 256, bulk_smem>>>(Wih1, b1);
    recur_kernel<<<rec_grid, 128, recur_smem>>>(1, Whh1, out);
}

// round 10
// speedup vs baseline: 4.3427x; 1.0267x over previous
#include <cuda_runtime.h>
#include <math.h>

typedef unsigned long long u64;
typedef unsigned int u32;

#define S_LEN 512
#define B_DIM 256
#define IN_DIM 256
#define BR_DIM 128
#define H_DIM 512
#define G_DIM 2048                 // 4*H
#define M_DIM (S_LEN * B_DIM)      // 131072

// ---------------- device scratch (no allocations allowed) ----------------
// gx layout: [(t*4+g)][h:512][b:256]  (transposed, 1 GiB)
__device__ float g_gx[(size_t)M_DIM * G_DIM];
// hs0 layout: [t][h:512][b:256]  (transposed, 256 MiB) -- doubles as layer-0 h history
__device__ float g_hs0[(size_t)S_LEN * H_DIM * B_DIM];
__device__ float g_h1t[2][H_DIM * B_DIM];               // layer-1 h double buffer, [h][b]

// per-b-column barrier state: 4 columns x 32 CTAs, slots padded to 128B lines
__device__ unsigned g_colcnt[4];
__device__ volatile unsigned g_slot[4][32][32];

// ---------------- packed f32x2 + activation helpers ----------------
__device__ __forceinline__ u64 pack2(float lo, float hi) {
    u64 r; asm("mov.b64 %0, {%1, %2};" : "=l"(r) : "f"(lo), "f"(hi)); return r;
}
__device__ __forceinline__ void unpack2(u64 v, float& lo, float& hi) {
    asm("mov.b64 {%0, %1}, %2;" : "=f"(lo), "=f"(hi) : "l"(v));
}
__device__ __forceinline__ void fma2(u64& d, u64 a, u64 b) {
    asm("fma.rn.f32x2 %0, %1, %2, %0;" : "+l"(d) : "l"(a), "l"(b));
}
__device__ __forceinline__ void add2(u64& d, u64 a) {
    asm("add.rn.f32x2 %0, %0, %1;" : "+l"(d) : "l"(a));
}
__device__ __forceinline__ float fast_sigmoid(float x) { return 1.0f / (1.0f + __expf(-x)); }
__device__ __forceinline__ float fast_tanh(float x) { return 1.0f - 2.0f / (__expf(2.0f * x) + 1.0f); }

// ---------------- cp.async ----------------
__device__ __forceinline__ u32 smem_u32(const void* p) {
    return (u32)__cvta_generic_to_shared(p);
}
#define CP16(d, s)  asm volatile("cp.async.cg.shared.global [%0], [%1], 16;" :: "r"(d), "l"(s))
#define CP4(d, s)   asm volatile("cp.async.ca.shared.global [%0], [%1], 4;"  :: "r"(d), "l"(s))
#define CPCOMMIT()  asm volatile("cp.async.commit_group;")
#define CPWAIT1()   asm volatile("cp.async.wait_group 1;")
#define CPWAIT0()   asm volatile("cp.async.wait_group 0;")

// ---------------- per-column barrier (32 CTAs, contention-free release) ----------------
__device__ __forceinline__ void gsync_col(int col, int myIdx, unsigned gen) {
    __syncthreads();
    if (threadIdx.x == 0) {
        __threadfence();
        unsigned a = atomicAdd(&g_colcnt[col], 1u);
        if (a == 31u) {
            g_colcnt[col] = 0;
            __threadfence();
            #pragma unroll
            for (int i = 0; i < 32; i++) g_slot[col][i][0] = gen;
        } else {
            volatile unsigned* s = &g_slot[col][myIdx][0];
            while (*s < gen) { }
        }
        __threadfence();
    }
    __syncthreads();
}

// ---------------- init (runs every replay; resets barrier state) ----------------
__global__ void __launch_bounds__(128, 1) init_kernel() {
    int tid = threadIdx.x;
    if (tid < 4) g_colcnt[tid] = 0;
    g_slot[tid >> 5][tid & 31][0] = 0;
}

// =====================================================================
// BULK GEMM: 128x128 CTA tile, 256 threads, 8x8 micro-tile, KC=16,
// 3-stage cp.async pipeline. Epilogue writes gx TRANSPOSED [t4g][h][b].
// =====================================================================
#define BKC 16
#define BST (BKC * 132)   // floats per stage per operand

template <int NC>
__device__ __forceinline__ void bulk_seg(
    u64 acc[8][4], const float* __restrict__ A, int ldA,
    const float* __restrict__ W, int mBase, int nBase,
    float* Asm, float* Bsm)
{
    const int tid = threadIdx.x;
    const int tx = tid & 15, ty = tid >> 4;

    u32 asb[3], bsb[3];
    #pragma unroll
    for (int s = 0; s < 3; s++) {
        asb[s] = smem_u32(Asm + s * BST);
        bsb[s] = smem_u32(Bsm + s * BST);
    }

    auto issue = [&](int c) {
        int s = c % 3;
        #pragma unroll
        for (int e = 0; e < 2; e++) {
            int id = tid + 256 * e;
            int k = id >> 5, s32 = id & 31;
            const float* src = W + (size_t)(c * BKC + k) * G_DIM + nBase + s32 * 4;
            CP16(bsb[s] + (u32)(k * 132 + s32 * 4) * 4, src);
        }
        #pragma unroll
        for (int e = 0; e < 8; e++) {
            int id = tid + 256 * e;
            int k = id & 15, r = id >> 4;
            const float* src = A + (size_t)(mBase + r) * ldA + c * BKC + k;
            CP4(asb[s] + (u32)(k * 132 + r) * 4, src);
        }
        CPCOMMIT();
    };

    issue(0); issue(1);
    CPWAIT1(); __syncthreads();

    #pragma unroll 1
    for (int c = 0; c < NC; c++) {
        if (c + 2 < NC) issue(c + 2);
        const float* Ap = Asm + (c % 3) * BST;
        const float* Bp = Bsm + (c % 3) * BST;
        #pragma unroll
        for (int k = 0; k < BKC; k++) {
            float4 a0 = *(const float4*)(Ap + k * 132 + ty * 8);
            float4 a1 = *(const float4*)(Ap + k * 132 + ty * 8 + 4);
            float4 b0 = *(const float4*)(Bp + k * 132 + tx * 8);
            float4 b1 = *(const float4*)(Bp + k * 132 + tx * 8 + 4);
            u64 w[4] = { pack2(b0.x, b0.y), pack2(b0.z, b0.w),
                         pack2(b1.x, b1.y), pack2(b1.z, b1.w) };
            float am[8] = { a0.x, a0.y, a0.z, a0.w, a1.x, a1.y, a1.z, a1.w };
            #pragma unroll
            for (int m = 0; m < 8; m++) {
                u64 aa = pack2(am[m], am[m]);
                #pragma unroll
                for (int np = 0; np < 4; np++) fma2(acc[m][np], w[np], aa);
            }
        }
        if (c + 2 < NC) { CPWAIT1(); } else { CPWAIT0(); }
        __syncthreads();
    }
}

// Writes gx transposed: gx[(t*4+g)][h][b] = acc + bias
__device__ __forceinline__ void bulk_epilogue(
    u64 acc[8][4], const float* __restrict__ bias, int mBase, int nBase)
{
    const int tid = threadIdx.x;
    const int tx = tid & 15, ty = tid >> 4;
    const int t = mBase >> 8;
    const int b0 = (mBase & 255) + ty * 8;

    float4 bb0 = *(const float4*)(bias + nBase + tx * 8);
    float4 bb1 = *(const float4*)(bias + nBase + tx * 8 + 4);
    float bcol[8] = { bb0.x, bb0.y, bb0.z, bb0.w, bb1.x, bb1.y, bb1.z, bb1.w };

    float f[8][8];
    #pragma unroll
    for (int m = 0; m < 8; m++) {
        #pragma unroll
        for (int np = 0; np < 4; np++) {
            float lo, hi;
            unpack2(acc[m][np], lo, hi);
            f[m][2 * np]     = lo + bcol[2 * np];
            f[m][2 * np + 1] = hi + bcol[2 * np + 1];
        }
    }
    #pragma unroll
    for (int nn = 0; nn < 8; nn++) {
        int n = nBase + tx * 8 + nn;
        int g = n >> 9, h = n & 511;
        float* dst = g_gx + (((size_t)(t * 4 + g)) * H_DIM + h) * B_DIM + b0;
        float4 v0 = make_float4(f[0][nn], f[1][nn], f[2][nn], f[3][nn]);
        float4 v1 = make_float4(f[4][nn], f[5][nn], f[6][nn], f[7][nn]);
        *(float4*)dst = v0;
        *(float4*)(dst + 4) = v1;
    }
}

// layer0: gx = bias0 + x@Wih0 + b@Wbh0
__global__ void __launch_bounds__(256, 2) bulk0_kernel(
    const float* __restrict__ x, const float* __restrict__ br,
    const float* __restrict__ Wih, const float* __restrict__ Wbh,
    const float* __restrict__ bias)
{
    extern __shared__ __align__(16) float sm[];
    float* Asm = sm;
    float* Bsm = sm + 3 * BST;
    const int nBase = blockIdx.x * 128;
    const int mBase = blockIdx.y * 128;

    u64 acc[8][4] = {};
    bulk_seg<IN_DIM / BKC>(acc, x, IN_DIM, Wih, mBase, nBase, Asm, Bsm);
    bulk_seg<BR_DIM / BKC>(acc, br, BR_DIM, Wbh, mBase, nBase, Asm, Bsm);
    bulk_epilogue(acc, bias, mBase, nBase);
}

// layer1: gx = bias1 + hs0@Wih1, with hs0 stored transposed [t][h][b]
__global__ void __launch_bounds__(256, 2) bulk1_kernel(
    const float* __restrict__ Wih, const float* __restrict__ bias)
{
    extern __shared__ __align__(16) float sm[];
    float* Asm = sm;
    float* Bsm = sm + 3 * BST;
    const int tid = threadIdx.x;
    const int nBase = blockIdx.x * 128;
    const int mBase = blockIdx.y * 128;
    const int t = mBase >> 8;
    const int bo = mBase & 255;

    u32 asb[3], bsb[3];
    #pragma unroll
    for (int s = 0; s < 3; s++) {
        asb[s] = smem_u32(Asm + s * BST);
        bsb[s] = smem_u32(Bsm + s * BST);
    }

    auto issue = [&](int c) {
        int s = c % 3;
        #pragma unroll
        for (int e = 0; e < 2; e++) {
            int id = tid + 256 * e;
            int k = id >> 5, s32 = id & 31;
            const float* src = Wih + (size_t)(c * BKC + k) * G_DIM + nBase + s32 * 4;
            CP16(bsb[s] + (u32)(k * 132 + s32 * 4) * 4, src);
        }
        // A from g_hs0[t][k][b] : k-major rows, CP16, no transpose
        #pragma unroll
        for (int e = 0; e < 2; e++) {
            int id = tid + 256 * e;
            int k = id >> 5, seg = id & 31;
            const float* src = g_hs0 + ((size_t)t * H_DIM + c * BKC + k) * B_DIM + bo + seg * 4;
            CP16(asb[s] + (u32)(k * 132 + seg * 4) * 4, src);
        }
        CPCOMMIT();
    };

    u64 acc[8][4] = {};
    issue(0); issue(1);
    CPWAIT1(); __syncthreads();

    const int tx = tid & 15, ty = tid >> 4;
    #pragma unroll 1
    for (int c = 0; c < H_DIM / BKC; c++) {
        if (c + 2 < H_DIM / BKC) issue(c + 2);
        const float* Ap = Asm + (c % 3) * BST;
        const float* Bp = Bsm + (c % 3) * BST;
        #pragma unroll
        for (int k = 0; k < BKC; k++) {
            float4 a0 = *(const float4*)(Ap + k * 132 + ty * 8);
            float4 a1 = *(const float4*)(Ap + k * 132 + ty * 8 + 4);
            float4 b0 = *(const float4*)(Bp + k * 132 + tx * 8);
            float4 b1 = *(const float4*)(Bp + k * 132 + tx * 8 + 4);
            u64 w[4] = { pack2(b0.x, b0.y), pack2(b0.z, b0.w),
                         pack2(b1.x, b1.y), pack2(b1.z, b1.w) };
            float am[8] = { a0.x, a0.y, a0.z, a0.w, a1.x, a1.y, a1.z, a1.w };
            #pragma unroll
            for (int m = 0; m < 8; m++) {
                u64 aa = pack2(am[m], am[m]);
                #pragma unroll
                for (int np = 0; np < 4; np++) fma2(acc[m][np], w[np], aa);
            }
        }
        if (c + 2 < H_DIM / BKC) { CPWAIT1(); } else { CPWAIT0(); }
        __syncthreads();
    }
    bulk_epilogue(acc, bias, mBase, nBase);
}

// =====================================================================
// RECURRENT persistent kernel. Grid: 32 h-CTAs (16 h each, all 4 gates)
// x 4 b-CTAs (64 b). 128 threads: thread (bq 0..15, hp 0..7) owns
// 4b x 2h x 4gates = 16 u64 accs. W (512k x 64 cols) persistent in smem
// [k][g][h16] (128 KB). A streamed [k][b] via CP16, 8 chunks of 64k,
// 3-stage pipeline. gx LDGs issued at step top, consumed AFTER the GEMM.
// Barrier is per-b-column (32 CTAs) with per-CTA padded release slots.
// =====================================================================
#define RKC 64
#define RAST (RKC * 68)          // A stage floats (pad 68 keeps 16B align)
#define RW_FLOATS (H_DIM * 64)   // 32768 floats = 128 KB

__global__ void __launch_bounds__(128, 1) recur_kernel(
    int layer, const float* __restrict__ Whh, float* __restrict__ out)
{
    extern __shared__ __align__(16) float sm[];
    float* Wsm = sm;                    // [k512][g4][h16]
    float* Asm = sm + RW_FLOATS;        // 3 stages of [k64][68]

    const int tid = threadIdx.x;
    const int bq = tid & 15;            // b = bt0 + 4*bq + {0..3}
    const int hp = tid >> 4;            // h = ht0 + 2*hp + {0,1}
    const int ht0 = blockIdx.x * 16;    // gridDim.x = 32
    const int bt0 = blockIdx.y * 64;    // gridDim.y = 4
    const int col = blockIdx.y;         // barrier column
    const int myIdx = blockIdx.x;       // index within column

    u32 wsb = smem_u32(Wsm);
    u32 asb[3];
    #pragma unroll
    for (int s = 0; s < 3; s++) asb[s] = smem_u32(Asm + s * RAST);

    // ---- load W once: Whh[k][g*512 + ht0 + h], dst [k][g*16 + h] ----
    #pragma unroll 8
    for (int e = 0; e < 64; e++) {
        int id = tid + 128 * e;
        int k = id >> 4, q = id & 15;   // q: g = q>>2, hquad = q&3
        const float* src = Whh + (size_t)k * G_DIM + (q >> 2) * H_DIM + ht0 + (q & 3) * 4;
        CP16(wsb + (u32)(k * 64 + q * 4) * 4, src);
    }
    CPCOMMIT(); CPWAIT0(); __syncthreads();

    float cst[4][2] = {};
    float hfin[4][2] = {};

    for (int t = 0; t < S_LEN; t++) {
        const float* Asrc = (layer == 0)
            ? g_hs0 + (size_t)(t - 1) * H_DIM * B_DIM
            : g_h1t[t & 1];

        auto issueA = [&](int c) {
            int s = c % 3;
            #pragma unroll
            for (int e = 0; e < 8; e++) {
                int id = tid + 128 * e;
                int k = id >> 4, seg = id & 15;
                const float* src = Asrc + (size_t)(c * RKC + k) * B_DIM + bt0 + seg * 4;
                CP16(asb[s] + (u32)(k * 68 + seg * 4) * 4, src);
            }
            CPCOMMIT();
        };

        if (t > 0) { issueA(0); issueA(1); }

        // ---- gx LDGs issued now, consumed only after the GEMM ----
        float4 gxv[8];
        const float* gxb = g_gx + (size_t)t * 4 * H_DIM * B_DIM;
        #pragma unroll
        for (int g = 0; g < 4; g++) {
            #pragma unroll
            for (int hh = 0; hh < 2; hh++) {
                gxv[g * 2 + hh] = *(const float4*)(
                    gxb + ((size_t)g * H_DIM + ht0 + 2 * hp + hh) * B_DIM + bt0 + 4 * bq);
            }
        }

        u64 acc[4][4] = {};  // [b][gate], pair over (h0,h1)

        if (t > 0) {
            CPWAIT1(); __syncthreads();

            #pragma unroll 1
            for (int c = 0; c < 8; c++) {
                if (c < 6) issueA(c + 2);
                const float* Ap = Asm + (c % 3) * RAST;
                const float* Wp = Wsm + c * (RKC * 64);
                #pragma unroll 8
                for (int k = 0; k < RKC; k++) {
                    float4 av = *(const float4*)(Ap + k * 68 + 4 * bq);
                    u64 w0 = *(const u64*)(Wp + k * 64 +  0 + 2 * hp);
                    u64 w1 = *(const u64*)(Wp + k * 64 + 16 + 2 * hp);
                    u64 w2 = *(const u64*)(Wp + k * 64 + 32 + 2 * hp);
                    u64 w3 = *(const u64*)(Wp + k * 64 + 48 + 2 * hp);
                    float am[4] = { av.x, av.y, av.z, av.w };
                    #pragma unroll
                    for (int b = 0; b < 4; b++) {
                        u64 aa = pack2(am[b], am[b]);
                        fma2(acc[b][0], w0, aa);
                        fma2(acc[b][1], w1, aa);
                        fma2(acc[b][2], w2, aa);
                        fma2(acc[b][3], w3, aa);
                    }
                }
                if (c < 6) { CPWAIT1(); } else { CPWAIT0(); }
                __syncthreads();
            }
        }

        // ---- add input-side preacts (gx) ----
        #pragma unroll
        for (int g = 0; g < 4; g++) {
            float* lo = (float*)&gxv[g * 2];
            float* hi = (float*)&gxv[g * 2 + 1];
            #pragma unroll
            for (int b = 0; b < 4; b++) add2(acc[b][g], pack2(lo[b], hi[b]));
        }

        // ---- gates ----
        #pragma unroll
        for (int b = 0; b < 4; b++) {
            float i0, i1, f0, f1, q0, q1, o0, o1;
            unpack2(acc[b][0], i0, i1);
            unpack2(acc[b][1], f0, f1);
            unpack2(acc[b][2], q0, q1);
            unpack2(acc[b][3], o0, o1);
            float c0 = fast_sigmoid(f0) * cst[b][0] + fast_sigmoid(i0) * fast_tanh(q0);
            float c1 = fast_sigmoid(f1) * cst[b][1] + fast_sigmoid(i1) * fast_tanh(q1);
            cst[b][0] = c0; cst[b][1] = c1;
            hfin[b][0] = fast_sigmoid(o0) * fast_tanh(c0);
            hfin[b][1] = fast_sigmoid(o1) * fast_tanh(c1);
        }

        // ---- stores ----
        if (layer == 0) {
            #pragma unroll
            for (int hh = 0; hh < 2; hh++) {
                float4 v = make_float4(hfin[0][hh], hfin[1][hh], hfin[2][hh], hfin[3][hh]);
                *(float4*)(g_hs0 + ((size_t)t * H_DIM + ht0 + 2 * hp + hh) * B_DIM
                           + bt0 + 4 * bq) = v;
            }
        } else {
            float* hb = g_h1t[(t + 1) & 1];
            #pragma unroll
            for (int hh = 0; hh < 2; hh++) {
                float4 v = make_float4(hfin[0][hh], hfin[1][hh], hfin[2][hh], hfin[3][hh]);
                *(float4*)(hb + ((size_t)(ht0 + 2 * hp + hh)) * B_DIM + bt0 + 4 * bq) = v;
            }
            #pragma unroll
            for (int b = 0; b < 4; b++) {
                *(float2*)(out + ((size_t)t * B_DIM + bt0 + 4 * bq + b) * H_DIM
                           + ht0 + 2 * hp) = make_float2(hfin[b][0], hfin[b][1]);
            }
        }

        gsync_col(col, myIdx, (layer == 0 ? 0u : (unsigned)S_LEN) + (unsigned)t + 1u);
    }

    // ---- finals: h_n, c_n ----
    const size_t base = (size_t)S_LEN * B_DIM * H_DIM;
    const size_t BH = (size_t)B_DIM * H_DIM;
    #pragma unroll
    for (int b = 0; b < 4; b++) {
        size_t row = (size_t)(bt0 + 4 * bq + b) * H_DIM + ht0 + 2 * hp;
        *(float2*)(out + base + (size_t)layer * BH + row) =
            make_float2(hfin[b][0], hfin[b][1]);
        *(float2*)(out + base + (2 + (size_t)layer) * BH + row) =
            make_float2(cst[b][0], cst[b][1]);
    }
}

// =====================================================================
extern "C" void kernel_launch(void* const* d_in, const int* in_sizes, int n_in,
                              void* d_out, int out_size)
{
    const float* x    = (const float*)d_in[0];  // [S, B, IN]
    const float* br   = (const float*)d_in[1];  // [S, B, BR]
    const float* Wih0 = (const float*)d_in[2];  // [IN, 4H]
    const float* Wbh0 = (const float*)d_in[3];  // [BR, 4H]
    const float* Whh0 = (const float*)d_in[4];  // [H, 4H]
    const float* b0   = (const float*)d_in[5];  // [4H]
    const float* Wih1 = (const float*)d_in[6];  // [H, 4H]
    const float* Whh1 = (const float*)d_in[7];  // [H, 4H]
    const float* b1   = (const float*)d_in[8];  // [4H]
    float* out = (float*)d_out;

    const int bulk_smem  = 3 * BST * 2 * sizeof(float);            // 50688
    const int recur_smem = (RW_FLOATS + 3 * RAST) * sizeof(float); // 183296

    cudaFuncSetAttribute(bulk0_kernel, cudaFuncAttributeMaxDynamicSharedMemorySize, bulk_smem);
    cudaFuncSetAttribute(bulk1_kernel, cudaFuncAttributeMaxDynamicSharedMemorySize, bulk_smem);
    cudaFuncSetAttribute(recur_kernel, cudaFuncAttributeMaxDynamicSharedMemorySize, recur_smem);

    init_kernel<<<1, 128>>>();

    dim3 bulk_grid(G_DIM / 128, M_DIM / 128);  // (16, 1024)
    dim3 rec_grid(H_DIM / 16, B_DIM / 64);     // (32, 4) = 128 CTAs

    bulk0_kernel<<<bulk_grid, 256, bulk_smem>>>(x, br, Wih0, Wbh0, b0);
    recur_kernel<<<rec_grid, 128, recur_smem>>>(0, Whh0, out);
    bulk1_kernel<<<bulk_grid, 256, bulk_smem>>>(Wih1, b1);
    recur_kernel<<<rec_grid, 128, recur_smem>>>(1, Whh1, out);
}